// round 4
// baseline (speedup 1.0000x reference)
#include <cuda_runtime.h>
#include <cstdint>

#define NTHREADS 128

// Fused packed-fp32 |x-w| accumulate. Weight operand is pre-negated, so the
// first add is the subtraction. In-place "+l" accumulator avoids MOV shuffles.
__device__ __forceinline__ void fused_abs_acc(uint64_t &acc, uint64_t xv, uint64_t wv){
    asm("{\n\t"
        ".reg .b64 t;\n\t"
        "add.rn.f32x2 t, %1, %2;\n\t"
        "and.b64 t, t, 0x7FFFFFFF7FFFFFFF;\n\t"
        "add.rn.f32x2 %0, %0, t;\n\t"
        "}\n" : "+l"(acc) : "l"(xv), "l"(wv));
}

__global__ __launch_bounds__(NTHREADS, 7)
void adder_kernel(const float* __restrict__ x,
                  const float* __restrict__ w,
                  const float* __restrict__ alpha,
                  float* __restrict__ out)
{
    // CTA: 16x16 spatial tile, 8 output channels, channels chunked by 4.
    // smem x tile stores each float DUPLICATED as an 8B (v,v) pair so the
    // packed x operand is one aligned LDS.64 at any pair index.
    // QSTRIDE=24 pairs: row-to-row bank-pair offset = 48 mod 32 = 16, so the
    // 4 rows touched by one warp cover banks pairwise-complementarily ->
    // conflict-free 2-wavefront LDS.64 for the xq loads.
    constexpr int QSTRIDE  = 24;
    constexpr int CH_PAIRS = 18 * QSTRIDE;      // 18 rows (16 + halo) per channel
    __shared__ __align__(16) uint64_t s_x2[4 * CH_PAIRS];  // 13.8 KB
    __shared__ __align__(16) uint64_t s_w2[64 * 9 * 4];    // negated o-pair weights: 18.4 KB

    const int tid  = threadIdx.x;
    const int bx   = blockIdx.x;
    const int b    = bx >> 7;          // 8 batches
    const int tile = (bx >> 3) & 15;   // 16 tiles (4x4 of 16x16)
    const int ob   = bx & 7;           // 8 o-blocks (fastest: x-tile L2 reuse)
    const int ti   = tile >> 2, tj = tile & 3;
    const int iloc = tid >> 3;         // 0..15 output row in tile
    const int jgrp = tid & 7;          // 0..7
    const int j0   = jgrp * 2;         // pair index; thread owns pixels j0, j0+1

    // ---- stage negated, o-pair-packed weights: s_w2[(c*9+tap)*4 + opair] ----
    // The 4 o-pairs of one (c,tap) are contiguous 32 B -> LDS.128-able.
    for (int e = tid; e < 64 * 9 * 4; e += NTHREADS) {
        int c   = e / 36;
        int r   = e - c * 36;
        int tap = r >> 2;
        int p   = r & 3;
        int o0  = ob * 8 + 2 * p;
        float lo = -w[(o0 * 64 + c) * 9 + tap];
        float hi = -w[((o0 + 1) * 64 + c) * 9 + tap];
        s_w2[e] = ((uint64_t)__float_as_uint(hi) << 32) | (uint64_t)__float_as_uint(lo);
    }

    const int gi0 = ti * 16 - 1;   // global row of smem row 0 (halo)
    const int gj0 = tj * 16 - 1;   // global col of smem pair-col 0 (halo)

    uint64_t acc[2][4];   // [pixel][opair]; each 32-bit half = one output's sum
    #pragma unroll
    for (int p = 0; p < 2; ++p)
        #pragma unroll
        for (int op = 0; op < 4; ++op) acc[p][op] = 0ull;

    #pragma unroll 1
    for (int ck = 0; ck < 16; ++ck) {
        __syncthreads();   // previous chunk's readers done (also covers weight staging)

        // ---- load chunk: 4 ch x 18 rows x 2 half-rows = 144 units of 9 cols ----
        #pragma unroll 1
        for (int u = tid; u < 144; u += NTHREADS) {
            int ci   = u / 36;
            int rem  = u - ci * 36;
            int r    = rem >> 1;
            int half = rem & 1;
            int gi   = gi0 + r;
            bool rowok = (unsigned)gi < 64u;
            const float* gp = x + (((b * 64 + ck * 4 + ci) * 64 + gi) * 64) + gj0 + half * 9;
            uint64_t* dst = s_x2 + ci * CH_PAIRS + r * QSTRIDE + half * 9;
            #pragma unroll
            for (int col = 0; col < 9; ++col) {
                bool ok = rowok && ((unsigned)(gj0 + half * 9 + col) < 64u);
                float v = ok ? gp[col] : 0.0f;         // zero halo == reference zero-pad
                uint32_t uu = __float_as_uint(v);
                dst[col] = ((uint64_t)uu << 32) | (uint64_t)uu;   // duplicated pair
            }
        }
        __syncthreads();

        // ---- compute 4 channels ----
        const uint64_t* wcb = s_w2 + ck * 4 * 36;
        #pragma unroll 1
        for (int cc = 0; cc < 4; ++cc) {
            const uint64_t* xc = s_x2 + cc * CH_PAIRS;
            const uint64_t* wc = wcb + cc * 36;
            #pragma unroll
            for (int kh = 0; kh < 3; ++kh) {
                uint64_t xq[4];
                #pragma unroll
                for (int m = 0; m < 4; ++m)
                    xq[m] = xc[(iloc + kh) * QSTRIDE + j0 + m];
                #pragma unroll
                for (int kw = 0; kw < 3; ++kw) {
                    // 4 o-pair weights in 2 broadcast LDS.128s
                    const ulonglong2 wv01 = *(const ulonglong2*)(wc + (kh * 3 + kw) * 4);
                    const ulonglong2 wv23 = *(const ulonglong2*)(wc + (kh * 3 + kw) * 4 + 2);
                    fused_abs_acc(acc[0][0], xq[kw],     wv01.x);
                    fused_abs_acc(acc[1][0], xq[kw + 1], wv01.x);
                    fused_abs_acc(acc[0][1], xq[kw],     wv01.y);
                    fused_abs_acc(acc[1][1], xq[kw + 1], wv01.y);
                    fused_abs_acc(acc[0][2], xq[kw],     wv23.x);
                    fused_abs_acc(acc[1][2], xq[kw + 1], wv23.x);
                    fused_abs_acc(acc[0][3], xq[kw],     wv23.y);
                    fused_abs_acc(acc[1][3], xq[kw + 1], wv23.y);
                }
            }
        }
    }

    // ---- epilogue: y = x - sum;  out = sign(y)*|y|^alpha (alpha==1 fast path) ----
    const float a = alpha[0];
    const int gi  = ti * 16 + iloc;
    const int gj  = tj * 16 + j0;
    const int base = ((b * 64 + ob * 8) * 64 + gi) * 64 + gj;

    #pragma unroll
    for (int op = 0; op < 4; ++op) {
        #pragma unroll
        for (int h = 0; h < 2; ++h) {
            int o = 2 * op + h;
            const float2 xv = *(const float2*)(x + base + o * 4096);
            uint32_t b0 = h ? (uint32_t)(acc[0][op] >> 32) : (uint32_t)acc[0][op];
            uint32_t b1 = h ? (uint32_t)(acc[1][op] >> 32) : (uint32_t)acc[1][op];
            float y0 = xv.x - __uint_as_float(b0);
            float y1 = xv.y - __uint_as_float(b1);
            float r0, r1;
            if (a == 1.0f) { r0 = y0; r1 = y1; }
            else {
                r0 = copysignf(powf(fabsf(y0), a), y0);
                r1 = copysignf(powf(fabsf(y1), a), y1);
            }
            *(float2*)(out + base + o * 4096) = make_float2(r0, r1);
        }
    }
}

extern "C" void kernel_launch(void* const* d_in, const int* in_sizes, int n_in,
                              void* d_out, int out_size)
{
    (void)in_sizes; (void)n_in; (void)out_size;
    const float* x     = (const float*)d_in[0];
    const float* wgt   = (const float*)d_in[1];
    const float* alpha = (const float*)d_in[2];
    float* out = (float*)d_out;
    // grid: 8 batches * 16 tiles(4x4 of 16x16) * 8 o-blocks = 1024 CTAs
    adder_kernel<<<1024, NTHREADS>>>(x, wgt, alpha, out);
}

// round 7
// speedup vs baseline: 1.3009x; 1.3009x over previous
#include <cuda_runtime.h>
#include <cstdint>

#define NTHREADS 128

// Fused packed-fp32 |x-w| accumulate. Weight operand is pre-negated, so the
// first add is the subtraction. In-place "+l" accumulator avoids MOV shuffles.
__device__ __forceinline__ void fused_abs_acc(uint64_t &acc, uint64_t xv, uint64_t wv){
    asm("{\n\t"
        ".reg .b64 t;\n\t"
        "add.rn.f32x2 t, %1, %2;\n\t"
        "and.b64 t, t, 0x7FFFFFFF7FFFFFFF;\n\t"
        "add.rn.f32x2 %0, %0, t;\n\t"
        "}\n" : "+l"(acc) : "l"(xv), "l"(wv));
}

// Build a duplicated (v,v) packed operand.
__device__ __forceinline__ uint64_t dup32(uint32_t v){
    uint64_t d;
    asm("mov.b64 %0, {%1, %1};" : "=l"(d) : "r"(v));
    return d;
}

__device__ __forceinline__ void cpasync16(uint32_t daddr, const float* g, int srcsize){
    asm volatile("cp.async.cg.shared.global [%0], [%1], 16, %2;"
                 :: "r"(daddr), "l"(g), "r"(srcsize));
}
__device__ __forceinline__ void cp_commit(){ asm volatile("cp.async.commit_group;"); }
template<int N> __device__ __forceinline__ void cp_wait(){
    asm volatile("cp.async.wait_group %0;" :: "n"(N));
}

// Stripe tile: 64 wide x 4 tall, 8 output channels per CTA, channels chunked by 4.
// smem x row layout (scalar floats, 72 per row):
//   idx 0..2 pad, idx 3 = left-halo zero, idx 4..67 = cols 0..63, idx 68 = right-halo
//   zero, idx 69..71 pad. Data starts at idx 4 (16B aligned for cp.async).
#define ROWF 72
#define CHF  (6 * ROWF)          // 6 rows (4 + halo) per channel
#define BUFF (4 * CHF)           // 4 channels per chunk = 1728 floats

__global__ __launch_bounds__(NTHREADS, 7)
void adder_kernel(const float* __restrict__ x,
                  const float* __restrict__ w,
                  const float* __restrict__ alpha,
                  float* __restrict__ out)
{
    __shared__ __align__(16) float    s_xf[2 * BUFF];       // 13.8 KB double-buffered
    __shared__ __align__(16) uint64_t s_w2[64 * 9 * 4];     // negated o-pair weights 18.4 KB

    const int tid  = threadIdx.x;
    const int bx   = blockIdx.x;
    const int b    = bx >> 7;          // 8 batches
    const int st   = (bx >> 3) & 15;   // 16 row-stripes of 4
    const int ob   = bx & 7;           // 8 o-blocks (fastest: x L2 reuse)
    const int rloc = tid >> 5;         // 0..3 output row in stripe
    const int jp   = tid & 31;         // pair index; pixels j0=2jp, j0+1
    const int R0   = st * 4;

    const uint32_t sbase = (uint32_t)__cvta_generic_to_shared(s_xf);

    // ---- kick off chunk 0 loads ASAP ----
    {
        #pragma unroll
        for (int k = 0; k < 3; ++k) {
            int u = tid + k * NTHREADS;                // 0..383
            int ci = u / 96, rem = u - ci * 96;
            int r = rem >> 4, q = rem & 15;
            int gi = R0 - 1 + r;
            const float* src = x + (((b * 64 + ci) * 64 + gi) * 64) + q * 4;
            uint32_t dst = sbase + ((ci * 6 + r) * ROWF + 4 + q * 4) * 4;
            cpasync16(dst, src, ((unsigned)gi < 64u) ? 16 : 0);
        }
        cp_commit();
    }

    // ---- persistent halo-zero pads (never overwritten by cp.async) ----
    for (int u = tid; u < 96; u += NTHREADS) {
        int side = u & 1, rr = u >> 1;       // 48 rows total (2 bufs * 24 rows)
        int buf = rr / 24, rem = rr - buf * 24;
        s_xf[buf * BUFF + rem * ROWF + (side ? 68 : 3)] = 0.0f;
    }

    // ---- stage negated, o-pair-packed weights: s_w2[(c*9+tap)*4 + opair] ----
    for (int e = tid; e < 64 * 9 * 4; e += NTHREADS) {
        int c   = e / 36;
        int r   = e - c * 36;
        int tap = r >> 2;
        int p   = r & 3;
        int o0  = ob * 8 + 2 * p;
        float lo = -w[(o0 * 64 + c) * 9 + tap];
        float hi = -w[((o0 + 1) * 64 + c) * 9 + tap];
        s_w2[e] = ((uint64_t)__float_as_uint(hi) << 32) | (uint64_t)__float_as_uint(lo);
    }

    uint64_t acc[2][4];   // [pixel][opair]; each 32-bit half = one output's sum
    #pragma unroll
    for (int p = 0; p < 2; ++p)
        #pragma unroll
        for (int op = 0; op < 4; ++op) acc[p][op] = 0ull;

    const int xoff = 2 + 2 * jp;   // even scalar idx; window covers cols j0-1..j0+2

    #pragma unroll 1
    for (int ck = 0; ck < 16; ++ck) {
        // prefetch next chunk into the other buffer
        if (ck < 15) {
            #pragma unroll
            for (int k = 0; k < 3; ++k) {
                int u = tid + k * NTHREADS;
                int ci = u / 96, rem = u - ci * 96;
                int r = rem >> 4, q = rem & 15;
                int gi = R0 - 1 + r;
                const float* src = x + (((b * 64 + (ck + 1) * 4 + ci) * 64 + gi) * 64) + q * 4;
                uint32_t dst = sbase + (((ck + 1) & 1) * BUFF + (ci * 6 + r) * ROWF + 4 + q * 4) * 4;
                cpasync16(dst, src, ((unsigned)gi < 64u) ? 16 : 0);
            }
            cp_commit();
            cp_wait<1>();     // current chunk's group done
        } else {
            cp_wait<0>();
        }
        __syncthreads();      // chunk ck visible to all warps

        // ---- compute 4 channels from buffer ck&1 ----
        const float*    xb  = s_xf + (ck & 1) * BUFF;
        const uint64_t* wcb = s_w2 + ck * 4 * 36;
        #pragma unroll 1
        for (int cc = 0; cc < 4; ++cc) {
            const uint64_t* wc = wcb + cc * 36;
            #pragma unroll
            for (int kh = 0; kh < 3; ++kh) {
                const float* p0 = xb + (cc * 6 + rloc + kh) * ROWF + xoff;
                const uint2 A = *(const uint2*)(p0);      // (pad/x, s0)
                const uint2 B = *(const uint2*)(p0 + 2);  // (s1, s2)
                const uint2 C = *(const uint2*)(p0 + 4);  // (s3, x)
                uint64_t d0 = dup32(A.y);   // col j0-1
                uint64_t d1 = dup32(B.x);   // col j0
                uint64_t d2 = dup32(B.y);   // col j0+1
                uint64_t d3 = dup32(C.x);   // col j0+2
                uint64_t xs[4] = {d0, d1, d2, d3};
                #pragma unroll
                for (int kw = 0; kw < 3; ++kw) {
                    const ulonglong2 wv01 = *(const ulonglong2*)(wc + (kh * 3 + kw) * 4);
                    const ulonglong2 wv23 = *(const ulonglong2*)(wc + (kh * 3 + kw) * 4 + 2);
                    fused_abs_acc(acc[0][0], xs[kw],     wv01.x);
                    fused_abs_acc(acc[1][0], xs[kw + 1], wv01.x);
                    fused_abs_acc(acc[0][1], xs[kw],     wv01.y);
                    fused_abs_acc(acc[1][1], xs[kw + 1], wv01.y);
                    fused_abs_acc(acc[0][2], xs[kw],     wv23.x);
                    fused_abs_acc(acc[1][2], xs[kw + 1], wv23.x);
                    fused_abs_acc(acc[0][3], xs[kw],     wv23.y);
                    fused_abs_acc(acc[1][3], xs[kw + 1], wv23.y);
                }
            }
        }
        __syncthreads();      // all reads of buf ck&1 done before it is refilled
    }

    // ---- epilogue: y = x - sum;  out = sign(y)*|y|^alpha (alpha==1 fast path) ----
    const float a = alpha[0];
    const int gi  = R0 + rloc;
    const int j0  = 2 * jp;
    const int base = ((b * 64 + ob * 8) * 64 + gi) * 64 + j0;

    #pragma unroll
    for (int op = 0; op < 4; ++op) {
        #pragma unroll
        for (int h = 0; h < 2; ++h) {
            int o = 2 * op + h;
            const float2 xv = *(const float2*)(x + base + o * 4096);
            uint32_t b0 = h ? (uint32_t)(acc[0][op] >> 32) : (uint32_t)acc[0][op];
            uint32_t b1 = h ? (uint32_t)(acc[1][op] >> 32) : (uint32_t)acc[1][op];
            float y0 = xv.x - __uint_as_float(b0);
            float y1 = xv.y - __uint_as_float(b1);
            float r0, r1;
            if (a == 1.0f) { r0 = y0; r1 = y1; }
            else {
                r0 = copysignf(powf(fabsf(y0), a), y0);
                r1 = copysignf(powf(fabsf(y1), a), y1);
            }
            *(float2*)(out + base + o * 4096) = make_float2(r0, r1);
        }
    }
}

extern "C" void kernel_launch(void* const* d_in, const int* in_sizes, int n_in,
                              void* d_out, int out_size)
{
    (void)in_sizes; (void)n_in; (void)out_size;
    const float* x     = (const float*)d_in[0];
    const float* wgt   = (const float*)d_in[1];
    const float* alpha = (const float*)d_in[2];
    float* out = (float*)d_out;
    // grid: 8 batches * 16 row-stripes(64x4) * 8 o-blocks = 1024 CTAs
    adder_kernel<<<1024, NTHREADS>>>(x, wgt, alpha, out);
}

// round 8
// speedup vs baseline: 1.6482x; 1.2670x over previous
#include <cuda_runtime.h>
#include <cuda_fp16.h>
#include <cstdint>

#define NTHREADS 128

// Fused packed-fp16 |x-w| accumulate. Weight operand is pre-negated, so the
// first add is the subtraction. abs of both halves = ONE 32-bit AND.
__device__ __forceinline__ void fused_h(uint32_t &acc, uint32_t xv, uint32_t wv){
    asm("{\n\t"
        ".reg .b32 t;\n\t"
        "add.rn.f16x2 t, %1, %2;\n\t"
        "and.b32 t, t, 0x7FFF7FFF;\n\t"
        "add.rn.f16x2 %0, %0, t;\n\t"
        "}\n" : "+r"(acc) : "r"(xv), "r"(wv));
}

// duplicated (v,v) half2 from one f32
__device__ __forceinline__ uint32_t f2dup(float v){
    uint32_t d;
    asm("cvt.rn.f16x2.f32 %0, %1, %1;" : "=r"(d) : "f"(v));
    return d;
}
// pack (lo,hi) floats into half2 with lo in low 16 bits (cvt: d = {src1=hi, src2=lo})
__device__ __forceinline__ uint32_t packh2(float lo, float hi){
    uint32_t d;
    asm("cvt.rn.f16x2.f32 %0, %1, %2;" : "=r"(d) : "f"(hi), "f"(lo));
    return d;
}
// unpack half2 into two f32
__device__ __forceinline__ void unpackh2(uint32_t h, float &lo, float &hi){
    asm("{\n\t.reg .b16 l, u;\n\tmov.b32 {l, u}, %2;\n\t"
        "cvt.f32.f16 %0, l;\n\tcvt.f32.f16 %1, u;\n\t}"
        : "=f"(lo), "=f"(hi) : "r"(h));
}

__device__ __forceinline__ void cpasync16(uint32_t daddr, const float* g, int srcsize){
    asm volatile("cp.async.cg.shared.global [%0], [%1], 16, %2;"
                 :: "r"(daddr), "l"(g), "r"(srcsize));
}
__device__ __forceinline__ void cp_commit(){ asm volatile("cp.async.commit_group;"); }
template<int N> __device__ __forceinline__ void cp_wait(){
    asm volatile("cp.async.wait_group %0;" :: "n"(N));
}

// Stripe tile: 64 wide x 4 tall, 8 output channels per CTA, channels chunked by 4.
// smem x row layout (scalar f32, 72 per row): idx 0..2 pad, idx 3 left-halo zero,
// idx 4..67 cols 0..63, idx 68 right-halo zero, idx 69..71 pad.
#define ROWF 72
#define CHF  (6 * ROWF)
#define BUFF (4 * CHF)

__global__ __launch_bounds__(NTHREADS, 7)
void adder_kernel(const float* __restrict__ x,
                  const float* __restrict__ w,
                  const float* __restrict__ alpha,
                  float* __restrict__ out)
{
    __shared__ __align__(16) float    s_xf[2 * BUFF];     // 13.8 KB double-buffered
    __shared__ __align__(16) uint32_t s_w2h[64 * 9 * 4];  // negated o-pair half2 weights 9.2 KB

    const int tid  = threadIdx.x;
    const int bx   = blockIdx.x;
    const int b    = bx >> 7;          // 8 batches
    const int st   = (bx >> 3) & 15;   // 16 row-stripes of 4
    const int ob   = bx & 7;           // 8 o-blocks (fastest: x L2 reuse)
    const int rloc = tid >> 5;         // 0..3 output row in stripe
    const int jp   = tid & 31;         // pair index; pixels j0=2jp, j0+1
    const int R0   = st * 4;

    const uint32_t sbase = (uint32_t)__cvta_generic_to_shared(s_xf);

    // ---- kick off chunk 0 loads ASAP ----
    {
        #pragma unroll
        for (int k = 0; k < 3; ++k) {
            int u = tid + k * NTHREADS;                // 0..383
            int ci = u / 96, rem = u - ci * 96;
            int r = rem >> 4, q = rem & 15;
            int gi = R0 - 1 + r;
            const float* src = x + (((b * 64 + ci) * 64 + gi) * 64) + q * 4;
            uint32_t dst = sbase + ((ci * 6 + r) * ROWF + 4 + q * 4) * 4;
            cpasync16(dst, src, ((unsigned)gi < 64u) ? 16 : 0);
        }
        cp_commit();
    }

    // ---- persistent halo-zero pads (never overwritten by cp.async) ----
    for (int u = tid; u < 96; u += NTHREADS) {
        int side = u & 1, rr = u >> 1;       // 48 rows total (2 bufs * 24 rows)
        int buf = rr / 24, rem = rr - buf * 24;
        s_xf[buf * BUFF + rem * ROWF + (side ? 68 : 3)] = 0.0f;
    }

    // ---- stage negated, o-pair half2 weights: s_w2h[(c*9+tap)*4 + opair] ----
    for (int e = tid; e < 64 * 9 * 4; e += NTHREADS) {
        int c   = e / 36;
        int r   = e - c * 36;
        int tap = r >> 2;
        int p   = r & 3;
        int o0  = ob * 8 + 2 * p;
        float lo = -w[(o0 * 64 + c) * 9 + tap];
        float hi = -w[((o0 + 1) * 64 + c) * 9 + tap];
        s_w2h[e] = packh2(lo, hi);
    }

    // fp32 master accumulators (merged once per chunk for precision)
    float accF[2][8];
    #pragma unroll
    for (int p = 0; p < 2; ++p)
        #pragma unroll
        for (int o = 0; o < 8; ++o) accF[p][o] = 0.0f;

    const int xoff = 2 + 2 * jp;   // even f32 idx; window covers cols j0-1..j0+2

    #pragma unroll 1
    for (int ck = 0; ck < 16; ++ck) {
        // prefetch next chunk into the other buffer
        if (ck < 15) {
            #pragma unroll
            for (int k = 0; k < 3; ++k) {
                int u = tid + k * NTHREADS;
                int ci = u / 96, rem = u - ci * 96;
                int r = rem >> 4, q = rem & 15;
                int gi = R0 - 1 + r;
                const float* src = x + (((b * 64 + (ck + 1) * 4 + ci) * 64 + gi) * 64) + q * 4;
                uint32_t dst = sbase + (((ck + 1) & 1) * BUFF + (ci * 6 + r) * ROWF + 4 + q * 4) * 4;
                cpasync16(dst, src, ((unsigned)gi < 64u) ? 16 : 0);
            }
            cp_commit();
            cp_wait<1>();     // current chunk's group done
        } else {
            cp_wait<0>();
        }
        __syncthreads();      // chunk ck visible to all warps

        // half2 chunk accumulators: 36 terms max per half -> fp16-safe window
        uint32_t acch[2][4];
        #pragma unroll
        for (int p = 0; p < 2; ++p)
            #pragma unroll
            for (int op = 0; op < 4; ++op) acch[p][op] = 0u;

        // ---- compute 4 channels from buffer ck&1 ----
        const float*     xb  = s_xf  + (ck & 1) * BUFF;
        const uint32_t*  wcb = s_w2h + ck * 4 * 36;
        #pragma unroll 1
        for (int cc = 0; cc < 4; ++cc) {
            const uint32_t* wc = wcb + cc * 36;
            #pragma unroll
            for (int kh = 0; kh < 3; ++kh) {
                const float* p0 = xb + (cc * 6 + rloc + kh) * ROWF + xoff;
                const float2 A = *(const float2*)(p0);      // (pad/x, col j0-1)
                const float2 B = *(const float2*)(p0 + 2);  // (col j0, col j0+1)
                const float2 C = *(const float2*)(p0 + 4);  // (col j0+2, pad/x)
                uint32_t xh[4];
                xh[0] = f2dup(A.y);
                xh[1] = f2dup(B.x);
                xh[2] = f2dup(B.y);
                xh[3] = f2dup(C.x);
                #pragma unroll
                for (int kw = 0; kw < 3; ++kw) {
                    const uint4 wq = *(const uint4*)(wc + (kh * 3 + kw) * 4);  // 4 o-pairs
                    fused_h(acch[0][0], xh[kw],     wq.x);
                    fused_h(acch[1][0], xh[kw + 1], wq.x);
                    fused_h(acch[0][1], xh[kw],     wq.y);
                    fused_h(acch[1][1], xh[kw + 1], wq.y);
                    fused_h(acch[0][2], xh[kw],     wq.z);
                    fused_h(acch[1][2], xh[kw + 1], wq.z);
                    fused_h(acch[0][3], xh[kw],     wq.w);
                    fused_h(acch[1][3], xh[kw + 1], wq.w);
                }
            }
        }

        // ---- merge chunk (fp16) into fp32 master accumulators ----
        #pragma unroll
        for (int p = 0; p < 2; ++p)
            #pragma unroll
            for (int op = 0; op < 4; ++op) {
                float lo, hi;
                unpackh2(acch[p][op], lo, hi);
                accF[p][2 * op]     += lo;
                accF[p][2 * op + 1] += hi;
            }

        __syncthreads();      // all reads of buf ck&1 done before it is refilled
    }

    // ---- epilogue: y = x - sum;  out = sign(y)*|y|^alpha (alpha==1 fast path) ----
    const float a = alpha[0];
    const int gi  = R0 + rloc;
    const int j0  = 2 * jp;
    const int base = ((b * 64 + ob * 8) * 64 + gi) * 64 + j0;

    #pragma unroll
    for (int o = 0; o < 8; ++o) {
        const float2 xv = *(const float2*)(x + base + o * 4096);
        float y0 = xv.x - accF[0][o];
        float y1 = xv.y - accF[1][o];
        float r0, r1;
        if (a == 1.0f) { r0 = y0; r1 = y1; }
        else {
            r0 = copysignf(powf(fabsf(y0), a), y0);
            r1 = copysignf(powf(fabsf(y1), a), y1);
        }
        *(float2*)(out + base + o * 4096) = make_float2(r0, r1);
    }
}

extern "C" void kernel_launch(void* const* d_in, const int* in_sizes, int n_in,
                              void* d_out, int out_size)
{
    (void)in_sizes; (void)n_in; (void)out_size;
    const float* x     = (const float*)d_in[0];
    const float* wgt   = (const float*)d_in[1];
    const float* alpha = (const float*)d_in[2];
    float* out = (float*)d_out;
    // grid: 8 batches * 16 row-stripes(64x4) * 8 o-blocks = 1024 CTAs
    adder_kernel<<<1024, NTHREADS>>>(x, wgt, alpha, out);
}